// round 14
// baseline (speedup 1.0000x reference)
#include <cuda_runtime.h>
#include <cstdint>

#define BATCH       64
#define SIZE        224
#define PIXELS      (SIZE*SIZE)        // 50176
#define DIM         40
#define NUM_CLASSES 10
#define WORDS       (PIXELS/32)        // 1568
#define NCHUNK      28                 // word chunks
#define CW          (WORDS/NCHUNK)     // 56 words per chunk
#define QPITCH      57                 // gcd(57,32)=1 -> conflict-free
#define BPB         4                  // batches per main block
#define NQUAD       (BATCH/BPB)        // 16
#define PPB         128                // pixels per pack block
#define NBP         (PIXELS/PPB)       // 392 pack blocks (bids 0..391)
#define PPC         (NBP/NCHUNK)       // 14 pack blocks per chunk
#define NMAIN       (NCHUNK*NQUAD)     // 448 main blocks
#define NTOT        (NBP+NMAIN)        // 840; 6/SM x 148 = 888 >= 840 co-resident

#define TILE_BYTES  (PPB*41*4)         // 20992 (pack tile)
#define SQ_BYTES    (DIM*QPITCH*4)     // 9120
#define SM_OFF      SQ_BYTES
#define BUF_BYTES   TILE_BYTES

// Deterministic global state; only flag counters are atomic (reset each run).
__device__ uint32_t g_Q[DIM * WORDS];                    // packed pos signs
__device__ int      g_TotCP[NBP * DIM];                  // per-pack-block Tot partials
__device__ int      g_Part[NCHUNK * NQUAD * BPB * DIM];  // AND-popc partials
__device__ int      g_CPart[NCHUNK * NQUAD * BPB];       // mask-popc partials
__device__ int      g_FlagC[NCHUNK];                     // per-chunk pack counters
__device__ int      g_FlagQ[NQUAD];                      // per-quad main counters
__device__ int      g_FlagDone = 0;                      // finisher counter

// ---------------------------------------------------------------------------
// Single fused kernel with FINE-GRAINED gating (no global barrier):
//  Pack role (bid<NBP): pos tile -> ballots -> g_Q + free per-block Tot
//    partials, then arrive on its chunk counter. Never waits.
//  Main role (c,bq): x-ballot first (overlaps pack DRAM), spin only on
//    g_FlagC[c]==14, stage Q chunk, AND+popc GEMM, write deterministic
//    partials, arrive on g_FlagQ[bq]. The 28th arriver for quad bq is that
//    quad's FINISHER: reduces its 4 batches + Tot, exact integer epilogue,
//    sign, classify, writes out[b0..b0+3]. 16 finishers run in parallel,
//    overlapped with other quads. 16th finisher resets flags (replay-safe).
//
// Exactness: pos/level are exactly {-1,+1}; NUM_LEVELS=2 -> idx=round(x) with
// half-to-even so level-1 <=> x>0.5 strictly. All sums to `enc` are exact
// integers -> bit-exact vs the reference fp32 math.
// ---------------------------------------------------------------------------
__global__ void __launch_bounds__(320, 6)
fused_kernel(const float* __restrict__ x,
             const float* __restrict__ pos,
             const float* __restrict__ lvl,
             const float* __restrict__ cls,
             float* __restrict__ out) {
    __shared__ __align__(16) char smemBuf[BUF_BYTES];   // aliased by role
    __shared__ int   sAcc[BPB][DIM];
    __shared__ int   sC[BPB];
    __shared__ int   sIsLast, sIsGLast;
    __shared__ int   sTotP[320];
    __shared__ int   sTotF[DIM];
    __shared__ int   sCq[BPB];
    __shared__ float encQ[BPB * DIM];

    const int tid  = threadIdx.x;
    const int lane = tid & 31;
    const int wid  = tid >> 5;                 // 10 warps

    if (blockIdx.x < NBP) {
        // ================= pack role =================
        float* tile = reinterpret_cast<float*>(smemBuf);         // PPB x 41
        const int p0 = blockIdx.x * PPB;
        const int p  = tid / DIM;
        const int d  = tid - p * DIM;
        const float* __restrict__ src = pos + (size_t)(p0 + p) * DIM + d;
        float* dst = &tile[p * 41 + d];
        #pragma unroll
        for (int k = 0; k < PPB / 8; k++)      // 16 coalesced loads/thread
            dst[k * (8 * 41)] = src[k * (8 * DIM)];
        __syncthreads();

        #pragma unroll
        for (int k = 0; k < 4; k++) {          // warp packs 4 dims x 4 words
            int dd = wid * 4 + k;
            unsigned q0 = __ballot_sync(0xffffffffu, tile[lane * 41 + dd]        > 0.0f);
            unsigned q1 = __ballot_sync(0xffffffffu, tile[(32 + lane) * 41 + dd] > 0.0f);
            unsigned q2 = __ballot_sync(0xffffffffu, tile[(64 + lane) * 41 + dd] > 0.0f);
            unsigned q3 = __ballot_sync(0xffffffffu, tile[(96 + lane) * 41 + dd] > 0.0f);
            if (lane == 0) {                   // p0/32 multiple of 4 -> 16B-aligned
                *reinterpret_cast<uint4*>(&g_Q[dd * WORDS + (p0 >> 5)]) =
                    make_uint4(q0, q1, q2, q3);
                g_TotCP[blockIdx.x * DIM + dd] =          // free Tot partial
                    __popc(q0) + __popc(q1) + __popc(q2) + __popc(q3);
            }
        }
        __threadfence();
        __syncthreads();
        if (tid == 0) atomicAdd(&g_FlagC[blockIdx.x / PPC], 1);
    } else {
        // ================= main role =================
        uint32_t* sQ = reinterpret_cast<uint32_t*>(smemBuf);
        uint32_t* sM = reinterpret_cast<uint32_t*>(smemBuf + SM_OFF);

        const int mb = blockIdx.x - NBP;
        const int c  = mb >> 4;                // chunk 0..27
        const int bq = mb & 15;
        const int b0 = bq * BPB;

        if (tid < DIM) {
            #pragma unroll
            for (int i = 0; i < BPB; i++) sAcc[i][tid] = 0;
        }
        if (tid < BPB) sC[tid] = 0;

        const int w0 = c * CW;
        int cc[BPB] = {0, 0, 0, 0};
        // Phase 1: x-ballot (no Q needed) — overlaps pack DRAM traffic.
        if (wid < 8) {
            const float* __restrict__ xb = x + (size_t)b0 * PIXELS + (size_t)w0 * 32;
            const int jbase = wid * (CW / 8);  // 7 words/warp
            #pragma unroll
            for (int jj = 0; jj < CW / 8; jj++) {
                int j = jbase + jj;
                #pragma unroll
                for (int i = 0; i < BPB; i++) {
                    float v = xb[(size_t)i * PIXELS + j * 32 + lane];
                    unsigned m = __ballot_sync(0xffffffffu, v > 0.5f);
                    cc[i] += __popc(m);
                    if (lane == 0) sM[i * CW + j] = m;
                }
            }
        }

        // Phase 2: wait ONLY for this chunk's 14 pack blocks.
        if (tid == 0) {
            volatile int* fp = &g_FlagC[c];
            while (*fp != PPC) { }
        }
        __syncthreads();
        __threadfence();                       // acquire pack writes

        // Phase 3: stage Q chunk (uint4).
        for (int i = tid; i < DIM * (CW / 4); i += 320) {
            int d = i / (CW / 4), j4 = i - d * (CW / 4);
            uint4 v = *reinterpret_cast<const uint4*>(&g_Q[d * WORDS + w0 + j4 * 4]);
            uint32_t* q = &sQ[d * QPITCH + j4 * 4];
            q[0] = v.x; q[1] = v.y; q[2] = v.z; q[3] = v.w;
        }
        __syncthreads();

        // Phase 4: AND+popc GEMM, per-lane dim accumulators -> shared reduce.
        if (wid < 8) {
            const int jbase = wid * (CW / 8);
            int aLo[BPB] = {0, 0, 0, 0};
            int aHi[BPB] = {0, 0, 0, 0};
            #pragma unroll
            for (int jj = 0; jj < CW / 8; jj++) {
                int j = jbase + jj;
                uint32_t q0 = sQ[lane * QPITCH + j];            // dim = lane
                #pragma unroll
                for (int i = 0; i < BPB; i++) aLo[i] += __popc(sM[i * CW + j] & q0);
                if (lane < 8) {
                    uint32_t q1 = sQ[(lane + 32) * QPITCH + j]; // dims 32..39
                    #pragma unroll
                    for (int i = 0; i < BPB; i++) aHi[i] += __popc(sM[i * CW + j] & q1);
                }
            }
            #pragma unroll
            for (int i = 0; i < BPB; i++) {
                atomicAdd(&sAcc[i][lane], aLo[i]);
                if (lane < 8) atomicAdd(&sAcc[i][lane + 32], aHi[i]);
                if (lane == 0) atomicAdd(&sC[i], cc[i]);
            }
        }
        __syncthreads();

        // Deterministic partial writes (no global atomics).
        if (tid < DIM) {
            #pragma unroll
            for (int i = 0; i < BPB; i++)
                g_Part[((c * NQUAD + bq) * BPB + i) * DIM + tid] = sAcc[i][tid];
        }
        if (tid < BPB) g_CPart[(c * NQUAD + bq) * BPB + tid] = sC[tid];

        __threadfence();
        __syncthreads();
        if (tid == 0) {
            int done = atomicAdd(&g_FlagQ[bq], 1);
            sIsLast = (done == NCHUNK - 1);
        }
        __syncthreads();

        // ============ quad finisher (28th arriver for this bq) ============
        if (sIsLast) {
            __threadfence();                   // acquire all writes for this quad

            // Tot: 392 x 40 partials, 8 groups x 40 dims = 320 threads.
            {
                int d = tid % DIM, g = tid / DIM;      // g in 0..7
                int s = 0;
                for (int r = g; r < NBP; r += 8) s += g_TotCP[r * DIM + d];
                sTotP[tid] = s;
            }
            if (tid < BPB) {
                int s = 0;
                #pragma unroll
                for (int c2 = 0; c2 < NCHUNK; c2++)
                    s += g_CPart[(c2 * NQUAD + bq) * BPB + tid];
                sCq[tid] = s;
            }
            __syncthreads();
            if (tid < DIM) {
                int s = 0;
                #pragma unroll
                for (int g = 0; g < 8; g++) s += sTotP[g * DIM + tid];
                sTotF[tid] = s;
            }
            __syncthreads();

            if (tid < BPB * DIM) {             // 160 (i,d) pairs
                int i = tid / DIM, d = tid - i * DIM;
                int s = 0;
                #pragma unroll
                for (int c2 = 0; c2 < NCHUNK; c2++)
                    s += g_Part[((c2 * NQUAD + bq) * BPB + i) * DIM + d];
                int A   = 2 * s - sCq[i];
                int Tot = 2 * sTotF[d] - PIXELS;
                float summed = lvl[d] * (float)(Tot - A) + lvl[DIM + d] * (float)A;
                encQ[tid] = (summed > 0.0f) ? 1.0f : -1.0f;
            }
            __syncthreads();

            if (tid < BPB * NUM_CLASSES) {     // 40 outputs
                int i = tid / NUM_CLASSES, cl = tid - i * NUM_CLASSES;
                float acc = 0.0f;
                #pragma unroll
                for (int d = 0; d < DIM; d++) acc += encQ[i * DIM + d] * cls[cl * DIM + d];
                out[(b0 + i) * NUM_CLASSES + cl] = acc;
            }

            // 16th finisher resets the flag counters for the next replay.
            __threadfence();
            __syncthreads();
            if (tid == 0) {
                int dn = atomicAdd(&g_FlagDone, 1);
                sIsGLast = (dn == NQUAD - 1);
            }
            __syncthreads();
            if (sIsGLast) {
                if (tid < NCHUNK) g_FlagC[tid] = 0;
                if (tid < NQUAD)  g_FlagQ[tid] = 0;
                if (tid == 0)     g_FlagDone = 0;
                __threadfence();
            }
        }
    }
}

// ---------------------------------------------------------------------------
extern "C" void kernel_launch(void* const* d_in, const int* in_sizes, int n_in,
                              void* d_out, int out_size) {
    const float* x   = (const float*)d_in[0];   // [64, 224, 224]
    const float* pos = (const float*)d_in[1];   // [50176, 40]
    const float* lvl = (const float*)d_in[2];   // [2, 40]
    const float* cls = (const float*)d_in[3];   // [10, 40]
    float* out = (float*)d_out;                 // [64, 10]

    fused_kernel<<<NTOT, 320>>>(x, pos, lvl, cls, out);
}

// round 16
// speedup vs baseline: 1.0243x; 1.0243x over previous
#include <cuda_runtime.h>
#include <cstdint>

#define BATCH       64
#define SIZE        224
#define PIXELS      (SIZE*SIZE)        // 50176
#define DIM         40
#define NUM_CLASSES 10
#define WORDS       (PIXELS/32)        // 1568
#define NCHUNK      28                 // word chunks in main kernel
#define CW          (WORDS/NCHUNK)     // 56 words per chunk (exact)
#define QPITCH      57                 // gcd(57,32)=1 -> conflict-free strides
#define BPB         4                  // batches per main block
#define NQUAD       (BATCH/BPB)        // 16
#define PPB         64                 // pixels per pack block
#define NBP         (PIXELS/PPB)       // 784 pack blocks

// Packed pos signs + deterministic partials. g_Tot/g_FlagQ/g_FlagDone start 0
// (static init) and are reset by the last finisher -> bit-exact across replays.
__device__ uint32_t g_Q[DIM * WORDS];                    // 251 KB
__device__ int      g_Tot[DIM];                          // popc(Q) per dim (atomic, int)
__device__ int      g_Part[NCHUNK * NQUAD * BPB * DIM];  // AND-popc partials
__device__ int      g_CPart[NCHUNK * NQUAD * BPB];       // mask-popc partials
__device__ int      g_FlagQ[NQUAD];                      // per-quad completion counters
__device__ int      g_FlagDone = 0;                      // finisher counter

// ---------------------------------------------------------------------------
// Kernel A (pack, R9-validated): 784 blocks x 64 pixels, 320 threads =
// 8 px x 40 dims. Fixed-increment coalesced loads -> pitch-41 transpose ->
// 8 ballots/warp -> uint2 store. Adds one deterministic int atomicAdd per
// (block,dim) for Tot (integer addition is associative -> bit-exact).
// Exactness: pos/level are exactly {-1,+1}; NUM_LEVELS=2 -> idx=round(x) with
// half-to-even so level-1 <=> x>0.5 strictly. All sums to `enc` are exact
// integers in both this kernel and the reference fp32 math.
// ---------------------------------------------------------------------------
__global__ void __launch_bounds__(320)
pack_pos_kernel(const float* __restrict__ pos) {
    __shared__ float tile[PPB * 41];          // 10.5 KB
    __shared__ int   sTot[DIM];
    const int tid  = threadIdx.x;
    const int lane = tid & 31;
    const int wid  = tid >> 5;                // 10 warps
    const int p0   = blockIdx.x * PPB;

    if (tid < DIM) sTot[tid] = 0;
    const int p = tid / DIM;                  // once
    const int d = tid - p * DIM;              // once
    const float* __restrict__ src = pos + (size_t)(p0 + p) * DIM + d;
    float* dst = &tile[p * 41 + d];
    #pragma unroll
    for (int k = 0; k < PPB / 8; k++)         // 8 coalesced loads/thread
        dst[k * (8 * 41)] = src[k * (8 * DIM)];
    __syncthreads();

    #pragma unroll
    for (int k = 0; k < 4; k++) {             // warp packs 4 dims x 2 words
        int dd = wid * 4 + k;
        unsigned q0 = __ballot_sync(0xffffffffu, tile[lane * 41 + dd]        > 0.0f);
        unsigned q1 = __ballot_sync(0xffffffffu, tile[(32 + lane) * 41 + dd] > 0.0f);
        if (lane == 0) {                      // p0/32 even -> 8B-aligned
            *reinterpret_cast<uint2*>(&g_Q[dd * WORDS + (p0 >> 5)]) = make_uint2(q0, q1);
            atomicAdd(&sTot[dd], __popc(q0) + __popc(q1));
        }
    }
    __syncthreads();
    if (tid < DIM) atomicAdd(&g_Tot[tid], sTot[tid]);
}

// ---------------------------------------------------------------------------
// Kernel B (R10-validated main + R14-validated quad finisher): block =
// (chunk c, quad bq). Stage Q chunk (uint4), x-ballot + AND+popc inline,
// per-lane dim accumulators, deterministic partial writes. The 28th arriver
// for quad bq runs that quad's epilogue (exact integer algebra + sign +
// classify) in-kernel; the 16th finisher resets all counters for replay.
// ---------------------------------------------------------------------------
__global__ void __launch_bounds__(256)
main_kernel(const float* __restrict__ x,
            const float* __restrict__ lvl,    // [2, DIM]
            const float* __restrict__ cls,    // [10, DIM]
            float* __restrict__ out) {        // [BATCH, 10]
    const int c  = blockIdx.x >> 4;           // 0..27 (same-chunk blocks adjacent)
    const int bq = blockIdx.x & 15;
    const int b0 = bq * BPB;
    const int tid  = threadIdx.x;
    const int lane = tid & 31;
    const int wid  = tid >> 5;                // 8 warps

    __shared__ uint32_t sQ[DIM * QPITCH];     // 9.1 KB
    __shared__ int   sAcc[BPB][DIM];
    __shared__ int   sC[BPB];
    __shared__ int   sIsLast, sIsGLast;
    __shared__ int   sTotF[DIM];
    __shared__ int   sCq[BPB];
    __shared__ float encQ[BPB * DIM];

    if (tid < DIM) {
        #pragma unroll
        for (int i = 0; i < BPB; i++) sAcc[i][tid] = 0;
    }
    if (tid < BPB) sC[tid] = 0;

    const int w0 = c * CW;
    // Stage Q chunk: 40 dims x 14 uint4.
    for (int i = tid; i < DIM * (CW / 4); i += 256) {
        int d = i / (CW / 4), j4 = i - d * (CW / 4);
        uint4 v = *reinterpret_cast<const uint4*>(&g_Q[d * WORDS + w0 + j4 * 4]);
        uint32_t* q = &sQ[d * QPITCH + j4 * 4];
        q[0] = v.x; q[1] = v.y; q[2] = v.z; q[3] = v.w;
    }
    __syncthreads();

    // GEMM: warp 'wid' covers words [wid*7, wid*7+7), 4 batches, inline ballots.
    const float* __restrict__ xb0 = x + (size_t)b0 * PIXELS + (size_t)w0 * 32;
    const int jbase = wid * (CW / 8);                  // 7 words/warp
    int aLo[BPB] = {0, 0, 0, 0};
    int aHi[BPB] = {0, 0, 0, 0};
    int cc[BPB]  = {0, 0, 0, 0};
    #pragma unroll
    for (int jj = 0; jj < CW / 8; jj++) {
        int j = jbase + jj;
        unsigned m[BPB];
        #pragma unroll
        for (int i = 0; i < BPB; i++) {
            float v = xb0[(size_t)i * PIXELS + j * 32 + lane];  // 128B coalesced
            m[i] = __ballot_sync(0xffffffffu, v > 0.5f);
            cc[i] += __popc(m[i]);
        }
        uint32_t q0 = sQ[lane * QPITCH + j];           // dim = lane
        #pragma unroll
        for (int i = 0; i < BPB; i++) aLo[i] += __popc(m[i] & q0);
        if (lane < 8) {
            uint32_t q1 = sQ[(lane + 32) * QPITCH + j];// dims 32..39
            #pragma unroll
            for (int i = 0; i < BPB; i++) aHi[i] += __popc(m[i] & q1);
        }
    }
    #pragma unroll
    for (int i = 0; i < BPB; i++) {
        atomicAdd(&sAcc[i][lane], aLo[i]);
        if (lane < 8) atomicAdd(&sAcc[i][lane + 32], aHi[i]);
        if (lane == 0) atomicAdd(&sC[i], cc[i]);
    }
    __syncthreads();

    // Deterministic partial writes.
    if (tid < DIM) {
        #pragma unroll
        for (int i = 0; i < BPB; i++)
            g_Part[((c * NQUAD + bq) * BPB + i) * DIM + tid] = sAcc[i][tid];
    }
    if (tid < BPB) g_CPart[(c * NQUAD + bq) * BPB + tid] = sC[tid];

    __threadfence();
    __syncthreads();
    if (tid == 0) {
        int done = atomicAdd(&g_FlagQ[bq], 1);
        sIsLast = (done == NCHUNK - 1);
    }
    __syncthreads();

    // ============ quad finisher (28th arriver for this bq) ============
    if (sIsLast) {
        __threadfence();                      // acquire all writes for this quad
        if (tid < BPB) {
            int s = 0;
            #pragma unroll
            for (int c2 = 0; c2 < NCHUNK; c2++)
                s += g_CPart[(c2 * NQUAD + bq) * BPB + tid];
            sCq[tid] = s;
        }
        if (tid < DIM) sTotF[tid] = g_Tot[tid];   // pack kernel fully reduced it
        __syncthreads();

        if (tid < BPB * DIM) {                // 160 (i,d) pairs
            int i = tid / DIM, d = tid - i * DIM;
            int s = 0;
            #pragma unroll
            for (int c2 = 0; c2 < NCHUNK; c2++)
                s += g_Part[((c2 * NQUAD + bq) * BPB + i) * DIM + d];
            int A   = 2 * s - sCq[i];         // sum of pos over masked pixels
            int Tot = 2 * sTotF[d] - PIXELS;  // sum of pos over all pixels
            float summed = lvl[d] * (float)(Tot - A) + lvl[DIM + d] * (float)A;
            encQ[tid] = (summed > 0.0f) ? 1.0f : -1.0f;
        }
        __syncthreads();

        if (tid < BPB * NUM_CLASSES) {        // 40 outputs
            int i = tid / NUM_CLASSES, cl = tid - i * NUM_CLASSES;
            float acc = 0.0f;
            #pragma unroll
            for (int d = 0; d < DIM; d++) acc += encQ[i * DIM + d] * cls[cl * DIM + d];
            out[(b0 + i) * NUM_CLASSES + cl] = acc;
        }

        // 16th finisher resets counters + g_Tot for the next graph replay.
        __threadfence();
        __syncthreads();
        if (tid == 0) {
            int dn = atomicAdd(&g_FlagDone, 1);
            sIsGLast = (dn == NQUAD - 1);
        }
        __syncthreads();
        if (sIsGLast) {
            if (tid < NQUAD) g_FlagQ[tid] = 0;
            if (tid < DIM)   g_Tot[tid]  = 0;
            if (tid == 0)    g_FlagDone  = 0;
            __threadfence();
        }
    }
}

// ---------------------------------------------------------------------------
extern "C" void kernel_launch(void* const* d_in, const int* in_sizes, int n_in,
                              void* d_out, int out_size) {
    const float* x   = (const float*)d_in[0];   // [64, 224, 224]
    const float* pos = (const float*)d_in[1];   // [50176, 40]
    const float* lvl = (const float*)d_in[2];   // [2, 40]
    const float* cls = (const float*)d_in[3];   // [10, 40]
    float* out = (float*)d_out;                 // [64, 10]

    pack_pos_kernel<<<NBP, 320>>>(pos);
    main_kernel<<<NCHUNK * NQUAD, 256>>>(x, lvl, cls, out);
}

// round 17
// speedup vs baseline: 1.2061x; 1.1776x over previous
#include <cuda_runtime.h>
#include <cstdint>

#define BATCH       64
#define SIZE        224
#define PIXELS      (SIZE*SIZE)        // 50176
#define DIM         40
#define NUM_CLASSES 10
#define WORDS       (PIXELS/32)        // 1568
#define NCHUNK      28                 // word chunks in main kernel
#define CW          (WORDS/NCHUNK)     // 56 words per chunk (exact)
#define QPITCH      57                 // gcd(57,32)=1 -> conflict-free strides
#define BPB         2                  // batches per main block
#define NPAIR       (BATCH/BPB)        // 32 -> grid 28*32 = 896 (6 blocks/SM)
#define PPB         64                 // pixels per pack block
#define NBP         (PIXELS/PPB)       // 784 pack blocks

// Packed pos sign bits + deterministic partials (every slot written every
// launch -> no zeroing, no global atomics, bit-exact across graph replays).
__device__ uint32_t g_Q[DIM * WORDS];              // 251 KB
__device__ int      g_TotPart[NCHUNK * DIM];       // popc(Q) per (chunk,d)
__device__ int      g_Part[NCHUNK * NPAIR * BPB * DIM];  // AND-popc partials
__device__ int      g_CPart[NCHUNK * NPAIR * BPB];       // popc(M) partials

// ---------------------------------------------------------------------------
// Kernel A (pack, R9-validated verbatim): 784 blocks x 64 pixels, 320 threads
// = 8 px x 40 dims. Fixed-increment coalesced loads -> pitch-41 transpose ->
// 8 ballots/warp -> uint2 store.
// Exactness: pos/level are exactly {-1,+1}; NUM_LEVELS=2 -> idx=round(x) with
// half-to-even so level-1 <=> x>0.5 strictly. All sums to `enc` are exact
// integers in both this kernel and the reference fp32 math.
// ---------------------------------------------------------------------------
__global__ void __launch_bounds__(320)
pack_pos_kernel(const float* __restrict__ pos) {
    __shared__ float tile[PPB * 41];          // 10.5 KB
    const int tid  = threadIdx.x;
    const int lane = tid & 31;
    const int wid  = tid >> 5;                // 10 warps
    const int p0   = blockIdx.x * PPB;

    const int p = tid / DIM;                  // once
    const int d = tid - p * DIM;              // once
    const float* __restrict__ src = pos + (size_t)(p0 + p) * DIM + d;
    float* dst = &tile[p * 41 + d];
    #pragma unroll
    for (int k = 0; k < PPB / 8; k++)         // 8 coalesced loads/thread
        dst[k * (8 * 41)] = src[k * (8 * DIM)];
    __syncthreads();

    #pragma unroll
    for (int k = 0; k < 4; k++) {             // warp packs 4 dims x 2 words
        int dd = wid * 4 + k;
        unsigned q0 = __ballot_sync(0xffffffffu, tile[lane * 41 + dd]        > 0.0f);
        unsigned q1 = __ballot_sync(0xffffffffu, tile[(32 + lane) * 41 + dd] > 0.0f);
        if (lane == 0)                        // p0/32 even -> 8B-aligned
            *reinterpret_cast<uint2*>(&g_Q[dd * WORDS + (p0 >> 5)]) = make_uint2(q0, q1);
    }
}

// ---------------------------------------------------------------------------
// Kernel B (R10 GEMM body, BPB=2 -> 896 blocks, 6/SM, 75% occ): block =
// (chunk c, pair bp). Stage Q chunk (uint4) -> inline x-ballot + AND+popc,
// per-lane dim accumulators; bp==0 blocks emit Tot partials from resident sQ.
// ---------------------------------------------------------------------------
__global__ void __launch_bounds__(256)
main_kernel(const float* __restrict__ x) {
    const int c  = blockIdx.x >> 5;           // 0..27 (same-chunk blocks adjacent)
    const int bp = blockIdx.x & 31;
    const int b0 = bp * BPB;
    const int tid  = threadIdx.x;
    const int lane = tid & 31;
    const int wid  = tid >> 5;                // 8 warps

    __shared__ uint32_t sQ[DIM * QPITCH];     // 9.1 KB
    __shared__ int sAcc[BPB][DIM];
    __shared__ int sC[BPB];

    if (tid < DIM) {
        #pragma unroll
        for (int i = 0; i < BPB; i++) sAcc[i][tid] = 0;
    }
    if (tid < BPB) sC[tid] = 0;

    const int w0 = c * CW;
    // Stage Q chunk: 40 dims x 14 uint4 = 560 vec loads.
    for (int i = tid; i < DIM * (CW / 4); i += 256) {
        int d = i / (CW / 4), j4 = i - d * (CW / 4);
        uint4 v = *reinterpret_cast<const uint4*>(&g_Q[d * WORDS + w0 + j4 * 4]);
        uint32_t* q = &sQ[d * QPITCH + j4 * 4];
        q[0] = v.x; q[1] = v.y; q[2] = v.z; q[3] = v.w;
    }
    __syncthreads();

    // GEMM: warp 'wid' covers words [wid*7, wid*7+7), 2 batches, inline ballots.
    const float* __restrict__ xb0 = x + (size_t)b0 * PIXELS + (size_t)w0 * 32;
    const int jbase = wid * (CW / 8);                  // 7 words/warp
    int aLo[BPB] = {0, 0};
    int aHi[BPB] = {0, 0};
    int cc[BPB]  = {0, 0};
    #pragma unroll
    for (int jj = 0; jj < CW / 8; jj++) {
        int j = jbase + jj;
        unsigned m[BPB];
        #pragma unroll
        for (int i = 0; i < BPB; i++) {
            float v = xb0[(size_t)i * PIXELS + j * 32 + lane];  // 128B coalesced
            m[i] = __ballot_sync(0xffffffffu, v > 0.5f);
            cc[i] += __popc(m[i]);
        }
        uint32_t q0 = sQ[lane * QPITCH + j];           // dim = lane
        #pragma unroll
        for (int i = 0; i < BPB; i++) aLo[i] += __popc(m[i] & q0);
        if (lane < 8) {
            uint32_t q1 = sQ[(lane + 32) * QPITCH + j];// dims 32..39
            #pragma unroll
            for (int i = 0; i < BPB; i++) aHi[i] += __popc(m[i] & q1);
        }
    }
    #pragma unroll
    for (int i = 0; i < BPB; i++) {
        atomicAdd(&sAcc[i][lane], aLo[i]);
        if (lane < 8) atomicAdd(&sAcc[i][lane + 32], aHi[i]);
        if (lane == 0) atomicAdd(&sC[i], cc[i]);
    }

    // Tot partials: the 28 bp==0 blocks popc their resident sQ chunk.
    if (bp == 0) {
        #pragma unroll
        for (int k = 0; k < DIM / 8; k++) {
            int d = wid + 8 * k;
            int t = 0;
            for (int j = lane; j < CW; j += 32)        // 1-2 words/lane
                t += __popc(sQ[d * QPITCH + j]);
            t = __reduce_add_sync(0xffffffffu, t);
            if (lane == 0) g_TotPart[c * DIM + d] = t;
        }
    }
    __syncthreads();

    if (tid < DIM) {
        #pragma unroll
        for (int i = 0; i < BPB; i++)
            g_Part[((c * NPAIR + bp) * BPB + i) * DIM + tid] = sAcc[i][tid];
    }
    if (tid < BPB) g_CPart[(c * NPAIR + bp) * BPB + tid] = sC[tid];
}

// ---------------------------------------------------------------------------
// Kernel C (R9-validated): 64 blocks (one per batch). Chunk-sum + exact
// integer epilogue + sign + classify.
// ---------------------------------------------------------------------------
__global__ void __launch_bounds__(64)
epilogue_kernel(const float* __restrict__ lvl,   // [2, DIM]
                const float* __restrict__ cls,   // [10, DIM]
                float* __restrict__ out) {       // [BATCH, 10]
    const int b   = blockIdx.x;
    const int tid = threadIdx.x;
    __shared__ float enc[DIM];
    __shared__ int   sCsum;

    if (tid == 0) {
        int s = 0;
        #pragma unroll
        for (int c = 0; c < NCHUNK; c++)
            s += g_CPart[(c * NPAIR + (b >> 1)) * BPB + (b & 1)];
        sCsum = s;
    }
    __syncthreads();

    if (tid < DIM) {
        int sA = 0, sT = 0;
        #pragma unroll
        for (int c = 0; c < NCHUNK; c++) {
            sA += g_Part[((c * NPAIR + (b >> 1)) * BPB + (b & 1)) * DIM + tid];
            sT += g_TotPart[c * DIM + tid];
        }
        int A   = 2 * sA - sCsum;           // sum of pos over masked pixels
        int Tot = 2 * sT - PIXELS;          // sum of pos over all pixels
        float summed = lvl[tid] * (float)(Tot - A) + lvl[DIM + tid] * (float)A;
        enc[tid] = (summed > 0.0f) ? 1.0f : -1.0f;
    }
    __syncthreads();

    if (tid < NUM_CLASSES) {
        float acc = 0.0f;
        #pragma unroll
        for (int d = 0; d < DIM; d++) acc += enc[d] * cls[tid * DIM + d];
        out[b * NUM_CLASSES + tid] = acc;
    }
}

// ---------------------------------------------------------------------------
extern "C" void kernel_launch(void* const* d_in, const int* in_sizes, int n_in,
                              void* d_out, int out_size) {
    const float* x   = (const float*)d_in[0];   // [64, 224, 224]
    const float* pos = (const float*)d_in[1];   // [50176, 40]
    const float* lvl = (const float*)d_in[2];   // [2, 40]
    const float* cls = (const float*)d_in[3];   // [10, 40]
    float* out = (float*)d_out;                 // [64, 10]

    pack_pos_kernel<<<NBP, 320>>>(pos);
    main_kernel<<<NCHUNK * NPAIR, 256>>>(x);
    epilogue_kernel<<<BATCH, 64>>>(lvl, cls, out);
}